// round 11
// baseline (speedup 1.0000x reference)
#include <cuda_runtime.h>
#include <math.h>

#define D_     196
#define NCH_   64
#define H_     8
#define DH_    64
#define INNER_ 512
#define MLP_   784
#define SEQ_   65
#define NG_QKV 384   // 1536/4
#define NG_D   49    // 196/4
#define NG_MLP 196   // 784/4
#define GRID_  52
#define NT_    512

// ---- scratch (__device__ globals; no allocations allowed) ----
__device__ float  g_a[NCH_ * D_];
__device__ float4 g_xatt4[SEQ_ * NG_D];
__device__ float4 g_qkv4[SEQ_ * NG_QKV];    // q(pre-scaled)|k|v
__device__ unsigned g_cnt;                  // barrier arrival counter (self-resetting)
__device__ unsigned g_gen;                  // barrier generation (monotonic)

__device__ __forceinline__ void fma4(float4& a, float h, const float4& w) {
    a.x += h * w.x; a.y += h * w.y; a.z += h * w.z; a.w += h * w.w;
}
__device__ __forceinline__ void add4(float4& a, const float4& b) {
    a.x += b.x; a.y += b.y; a.z += b.z; a.w += b.w;
}
__device__ __forceinline__ float gelu_exact(float v) {
    return 0.5f * v * (1.f + erff(v * 0.70710678118654752f));
}

// grid-wide barrier: gridDim.x (52) <= #SMs (148), 1 block/SM -> co-resident, no deadlock.
__device__ __forceinline__ void gsync() {
    __syncthreads();
    if (threadIdx.x == 0) {
        unsigned gen = *(volatile unsigned*)&g_gen;
        __threadfence();
        if (atomicAdd(&g_cnt, 1u) == gridDim.x - 1u) {
            atomicExch(&g_cnt, 0u);
            __threadfence();
            atomicAdd(&g_gen, 1u);
        } else {
            while (*(volatile unsigned*)&g_gen == gen) { __nanosleep(32); }
        }
        __threadfence();
    }
    __syncthreads();
}

__global__ __launch_bounds__(NT_, 1) void k_fused(
    const float* __restrict__ x, const float* __restrict__ tokens,
    const float* __restrict__ x_pe, const float* __restrict__ conv_k,
    const float* __restrict__ bn_g, const float* __restrict__ bn_b,
    const float* __restrict__ bn_rm, const float* __restrict__ bn_rv,
    const float* __restrict__ fc_w1, const float* __restrict__ fc_w2,
    const float* __restrict__ ln1_g, const float* __restrict__ ln1_b,
    const float4* __restrict__ wqkv4,
    const float4* __restrict__ wout4, const float4* __restrict__ bout4,
    const float4* __restrict__ ln2g4, const float4* __restrict__ ln2b4,
    const float4* __restrict__ ffw1_4, const float4* __restrict__ ffb1_4,
    const float4* __restrict__ ffw2_4, const float4* __restrict__ ffb2_4,
    float4* __restrict__ out4)
{
    __shared__ __align__(16) char sm[40000];
    const int tid = threadIdx.x;
    const int b   = blockIdx.x;

    // ============ PHASE A: LN1 + QKV, 4 rows/block (blocks 0..50) + gating (51) ============
    if (b < 51) {
        float*  hs   = (float*)sm;                 // 4*196 f  [0,3136)
        float4* red  = (float4*)(sm + 3200);       // 3 slices * 128 gl * 4 rows  [3200,27776)
        float*  mrow = (float*)(sm + 27776);       // 4
        float*  rrow = (float*)(sm + 27808);       // 4

        const int tile  = b / 3;                   // 0..16
        const int chunk = b - tile * 3;            // 0..2
        const int base  = tile * 4;                // rows base..base+3

        for (int idx = tid; idx < 4 * D_; idx += NT_) {
            int r = idx / D_, c = idx - r * D_;
            int row = base + r;
            hs[idx] = (row < SEQ_) ? x[row * D_ + c] : 0.f;
        }
        __syncthreads();

        const int warp = tid >> 5, lane = tid & 31;
        if (warp < 4) {
            float s1 = 0.f, s2 = 0.f;
            #pragma unroll
            for (int i = 0; i < 7; i++) {
                int c = lane + 32 * i;
                if (c < D_) { float v = hs[warp * D_ + c]; s1 += v; s2 += v * v; }
            }
            #pragma unroll
            for (int o = 16; o; o >>= 1) {
                s1 += __shfl_down_sync(0xffffffffu, s1, o);
                s2 += __shfl_down_sync(0xffffffffu, s2, o);
            }
            if (lane == 0) {
                float mean = s1 * (1.f / 196.f);
                float var  = s2 * (1.f / 196.f) - mean * mean;
                mrow[warp] = mean; rrow[warp] = rsqrtf(var + 1e-5f);
            }
        }
        __syncthreads();
        for (int idx = tid; idx < 4 * D_; idx += NT_) {
            int r = idx / D_, c = idx - r * D_;
            hs[idx] = (hs[idx] - mrow[r]) * rrow[r] * ln1_g[c] + ln1_b[c];
        }
        __syncthreads();

        const int gl = tid & 127;
        const int g  = chunk * 128 + gl;     // < 384
        const int s  = tid >> 7;             // K-slice 0..3, each 49
        float4 a0 = make_float4(0.f,0.f,0.f,0.f), a1 = a0, a2 = a0, a3 = a0;

        const int kb = s * 49;
        const float4* W = wqkv4 + kb * NG_QKV + g;
        #pragma unroll 7
        for (int k = 0; k < 49; k++) {
            float4 w = W[k * NG_QKV];
            fma4(a0, hs[kb + k], w);
            fma4(a1, hs[D_ + kb + k], w);
            fma4(a2, hs[2 * D_ + kb + k], w);
            fma4(a3, hs[3 * D_ + kb + k], w);
        }
        if (s > 0) {
            float4* rp = red + ((s - 1) * 128 + gl) * 4;
            rp[0] = a0; rp[1] = a1; rp[2] = a2; rp[3] = a3;
        }
        __syncthreads();
        if (s == 0) {
            #pragma unroll
            for (int ss = 0; ss < 3; ss++) {
                const float4* rp = red + (ss * 128 + gl) * 4;
                add4(a0, rp[0]); add4(a1, rp[1]); add4(a2, rp[2]); add4(a3, rp[3]);
            }
            float sc = (g < 128) ? 0.125f : 1.f;   // q pre-scale DH^-0.5
            a0.x*=sc; a0.y*=sc; a0.z*=sc; a0.w*=sc;
            a1.x*=sc; a1.y*=sc; a1.z*=sc; a1.w*=sc;
            a2.x*=sc; a2.y*=sc; a2.z*=sc; a2.w*=sc;
            a3.x*=sc; a3.y*=sc; a3.z*=sc; a3.w*=sc;
            if (base     < SEQ_) g_qkv4[(base    ) * NG_QKV + g] = a0;
            if (base + 1 < SEQ_) g_qkv4[(base + 1) * NG_QKV + g] = a1;
            if (base + 2 < SEQ_) g_qkv4[(base + 2) * NG_QKV + g] = a2;
            if (base + 3 < SEQ_) g_qkv4[(base + 3) * NG_QKV + g] = a3;
        }
    } else {
        // ---------------- gating (block 51) ----------------
        float* b1s = (float*)sm;              // 64
        float* b2s = (float*)(sm + 256);      // 64
        float* hid = (float*)(sm + 512);      // 12
        float* cs  = (float*)(sm + 576);      // 64

        const int warp = tid >> 5, lane = tid & 31;
        const float k0 = conv_k[3], k1 = conv_k[4], k2 = conv_k[5];
        const float rm  = bn_rm[0];
        const float inv = rsqrtf(bn_rv[0] + 1e-5f) * bn_g[0];
        const float bb  = bn_b[0];

        for (int ch = warp; ch < NCH_; ch += 16) {
            const float* row = x_pe + ch * D_;
            float s = 0.f;
            for (int d = lane; d < D_; d += 32) {
                float xm = (d > 0)      ? row[d - 1] : 0.f;
                float xc = row[d];
                float xp = (d < D_ - 1) ? row[d + 1] : 0.f;
                float conv = k0 * xm + k1 * xc + k2 * xp;
                float bn = (conv - rm) * inv + bb;
                float av = fmaxf(bn, 0.f);
                g_a[ch * D_ + d] = av;
                s += av;
            }
            #pragma unroll
            for (int o = 16; o; o >>= 1) s += __shfl_down_sync(0xffffffffu, s, o);
            if (lane == 0) b1s[ch] = s * (1.f / 196.f);
        }
        __syncthreads();

        if (tid < NCH_) {
            const float bi = b1s[tid];
            float mx = -1e30f, mn = 1e30f;
            int cnt_nonpos = 0, rank = 0;
            #pragma unroll 8
            for (int j = 0; j < NCH_; j++) {
                float bj = b1s[j];
                mx = fmaxf(mx, bj); mn = fminf(mn, bj);
                if (bj <= 0.f) cnt_nonpos++;
                if (bj < bi || (bj == bi && j < tid)) rank++;
            }
            int middle = (mx < 0.f || mn > 0.f) ? 32 : (mx > 0.f ? cnt_nonpos : 0);
            float b2;
            if (rank < middle) {
                float ls = (float)middle;
                b2 = bi - 1.f / (1.f + powf(ls, bi));
            } else {
                float le = (float)(NCH_ - middle);
                b2 = bi + 1.f / (1.f + powf(le, -bi));
            }
            b2s[tid] = b2;
        }
        __syncthreads();
        if (tid < 12) {
            float s = 0.f;
            #pragma unroll 8
            for (int i = 0; i < NCH_; i++) s += b2s[i] * fc_w1[i * 12 + tid];
            hid[tid] = fmaxf(s, 0.f);
        }
        __syncthreads();
        if (tid < NCH_) {
            float s = 0.f;
            #pragma unroll
            for (int j = 0; j < 12; j++) s += hid[j] * fc_w2[j * NCH_ + tid];
            cs[tid] = 1.f / (1.f + expf(-s));
        }
        __syncthreads();
        float* xatt = (float*)g_xatt4;
        for (int idx = tid; idx < NCH_ * D_; idx += NT_)
            xatt[idx] = g_a[idx] * cs[idx / D_];
        for (int d = tid; d < D_; d += NT_)
            xatt[NCH_ * D_ + d] = tokens[d];
    }
    gsync();   // the ONLY grid barrier

    // ============ PHASE B: 2 token rows per block (blocks 0..32) ============
    if (b >= 33) return;
    const int n0 = 2 * b;
    const int n1 = 2 * b + 1;
    const bool v1 = (n1 < SEQ_);
    const float* qkv = (const float*)g_qkv4;

    float*  qs    = (float*)sm;                // 2*512 f     [0,4096)
    float*  scs   = (float*)(sm + 4096);       // 2*8*66 f    [4096,8320)
    float*  smaxp = (float*)(sm + 8320);       // 16
    float*  sinvp = (float*)(sm + 8384);       // 16
    float*  os    = (float*)(sm + 8448);       // 2*512 f     [8448,12544)
    float4* red2  = (float4*)(sm + 12544);     // 7*49*2 f4   [12544,23520)
    float4* x2s   = (float4*)(sm + 23520);     // 2*49 f4     [23520,25088)
    float4* h2s   = (float4*)(sm + 25088);     // 2*49 f4     [25088,26656)
    float*  p1    = (float*)(sm + 26656);      // 2*49
    float*  p2    = (float*)(sm + 27048);      // 2*49
    float*  stats = (float*)(sm + 27440);      // 4
    float4* ts4   = (float4*)(sm + 27456);     // 2*196 f4    [27456,33728)
    float4* red1  = (float4*)(sm + 33728);     // 2*196 f4    [33728,40000)

    // ---- attention: head h = tid>>6, d = tid&63; both rows share K/V loads ----
    const int h = tid >> 6, d = tid & 63;
    qs[tid]       = qkv[n0 * 1536 + tid];
    qs[512 + tid] = v1 ? qkv[n1 * 1536 + tid] : 0.f;
    __syncthreads();

    const float* qh0 = qs + h * DH_;
    const float* qh1 = qs + 512 + h * DH_;
    {
        const float4* kr = (const float4*)(qkv + d * 1536 + INNER_ + h * DH_);
        float s0 = 0.f, s1 = 0.f;
        #pragma unroll
        for (int i = 0; i < 16; i++) {
            float4 k4 = kr[i];
            s0 += qh0[4*i]*k4.x + qh0[4*i+1]*k4.y + qh0[4*i+2]*k4.z + qh0[4*i+3]*k4.w;
            s1 += qh1[4*i]*k4.x + qh1[4*i+1]*k4.y + qh1[4*i+2]*k4.z + qh1[4*i+3]*k4.w;
        }
        scs[h * 66 + d]       = s0;
        scs[528 + h * 66 + d] = s1;
        if (d == 0) {
            const float4* kr2 = (const float4*)(qkv + 64 * 1536 + INNER_ + h * DH_);
            float t0 = 0.f, t1 = 0.f;
            #pragma unroll
            for (int i = 0; i < 16; i++) {
                float4 k4 = kr2[i];
                t0 += qh0[4*i]*k4.x + qh0[4*i+1]*k4.y + qh0[4*i+2]*k4.z + qh0[4*i+3]*k4.w;
                t1 += qh1[4*i]*k4.x + qh1[4*i+1]*k4.y + qh1[4*i+2]*k4.z + qh1[4*i+3]*k4.w;
            }
            scs[h * 66 + 64]       = t0;
            scs[528 + h * 66 + 64] = t1;
        }
    }
    __syncthreads();
    {   // max: warp (h, d<32) -> row0, warp (h, d>=32) -> row1
        const int row = d >> 5, lane = d & 31;
        float* sr = scs + row * 528 + h * 66;
        float m = fmaxf(sr[lane], sr[lane + 32]);
        if (lane == 0) m = fmaxf(m, sr[64]);
        #pragma unroll
        for (int o = 16; o; o >>= 1) m = fmaxf(m, __shfl_down_sync(0xffffffffu, m, o));
        if (lane == 0) smaxp[row * 8 + h] = m;
    }
    __syncthreads();
    {
        float mx0 = smaxp[h], mx1 = smaxp[8 + h];
        scs[h * 66 + d]       = expf(scs[h * 66 + d] - mx0);
        scs[528 + h * 66 + d] = expf(scs[528 + h * 66 + d] - mx1);
        if (d == 0) {
            scs[h * 66 + 64]       = expf(scs[h * 66 + 64] - mx0);
            scs[528 + h * 66 + 64] = expf(scs[528 + h * 66 + 64] - mx1);
        }
    }
    __syncthreads();
    {
        const int row = d >> 5, lane = d & 31;
        float* sr = scs + row * 528 + h * 66;
        float s = sr[lane] + sr[lane + 32];
        if (lane == 0) s += sr[64];
        #pragma unroll
        for (int o = 16; o; o >>= 1) s += __shfl_down_sync(0xffffffffu, s, o);
        if (lane == 0) sinvp[row * 8 + h] = 1.f / s;
    }
    __syncthreads();
    {
        const float* vb = qkv + 2 * INNER_ + h * DH_ + d;
        const float* p0 = scs + h * 66;
        const float* pr1 = scs + 528 + h * 66;
        float a0 = 0.f, a1 = 0.f;
        #pragma unroll 8
        for (int m = 0; m < SEQ_; m++) {
            float vv = vb[m * 1536];
            a0 += p0[m] * vv;
            a1 += pr1[m] * vv;
        }
        os[tid]       = a0 * sinvp[h];
        os[512 + tid] = a1 * sinvp[8 + h];
    }
    __syncthreads();

    // ---- out-proj (K=512, 8 slices of 64) + residuals + LN2 ----
    const int s8 = tid / NG_D;                 // 0..10 (use <8)
    const int g  = tid - s8 * NG_D;            // <49
    float4 v0 = make_float4(0.f,0.f,0.f,0.f), vr1 = v0;
    if (s8 < 8) {
        const int kb = s8 * 64;
        const float4* W = wout4 + kb * NG_D + g;
        const float* h0 = os + kb;
        const float* h1 = os + 512 + kb;
        #pragma unroll 8
        for (int k = 0; k < 64; k++) {
            float4 w = W[k * NG_D];
            fma4(v0, h0[k], w);
            fma4(vr1, h1[k], w);
        }
        if (s8 > 0) {
            red2[((s8 - 1) * NG_D + g) * 2 + 0] = v0;
            red2[((s8 - 1) * NG_D + g) * 2 + 1] = vr1;
        }
    }
    __syncthreads();
    if (s8 == 0) {
        #pragma unroll
        for (int ss = 0; ss < 7; ss++) {
            add4(v0,  red2[(ss * NG_D + g) * 2 + 0]);
            add4(vr1, red2[(ss * NG_D + g) * 2 + 1]);
        }
        float4 bo = bout4[g];
        float4 xv0 = ((const float4*)x)[n0 * NG_D + g];
        float4 xa0 = g_xatt4[n0 * NG_D + g];
        float4 xv1 = make_float4(0.f,0.f,0.f,0.f), xa1 = xv1;
        if (v1) {
            xv1 = ((const float4*)x)[n1 * NG_D + g];
            xa1 = g_xatt4[n1 * NG_D + g];
        }
        v0.x += bo.x + xv0.x + xa0.x; v0.y += bo.y + xv0.y + xa0.y;
        v0.z += bo.z + xv0.z + xa0.z; v0.w += bo.w + xv0.w + xa0.w;
        vr1.x += bo.x + xv1.x + xa1.x; vr1.y += bo.y + xv1.y + xa1.y;
        vr1.z += bo.z + xv1.z + xa1.z; vr1.w += bo.w + xv1.w + xa1.w;
        x2s[g]       = v0;
        x2s[NG_D + g] = vr1;
        p1[g]        = v0.x + v0.y + v0.z + v0.w;
        p2[g]        = v0.x*v0.x + v0.y*v0.y + v0.z*v0.z + v0.w*v0.w;
        p1[NG_D + g] = vr1.x + vr1.y + vr1.z + vr1.w;
        p2[NG_D + g] = vr1.x*vr1.x + vr1.y*vr1.y + vr1.z*vr1.z + vr1.w*vr1.w;
    }
    __syncthreads();
    if (tid < 64) {
        const int row = tid >> 5, lane = tid & 31;
        float t1 = 0.f, t2 = 0.f;
        for (int i = lane; i < NG_D; i += 32) { t1 += p1[row * NG_D + i]; t2 += p2[row * NG_D + i]; }
        #pragma unroll
        for (int o = 16; o; o >>= 1) {
            t1 += __shfl_down_sync(0xffffffffu, t1, o);
            t2 += __shfl_down_sync(0xffffffffu, t2, o);
        }
        if (lane == 0) {
            float mean = t1 * (1.f / 196.f);
            float var  = t2 * (1.f / 196.f) - mean * mean;
            stats[row * 2]     = mean;
            stats[row * 2 + 1] = rsqrtf(var + 1e-5f);
        }
    }
    __syncthreads();
    if (s8 == 0) {
        float4 gg = ln2g4[g], bb = ln2b4[g];
        {
            float m = stats[0], rs = stats[1];
            float4 v = x2s[g], hh;
            hh.x = (v.x - m) * rs * gg.x + bb.x;
            hh.y = (v.y - m) * rs * gg.y + bb.y;
            hh.z = (v.z - m) * rs * gg.z + bb.z;
            hh.w = (v.w - m) * rs * gg.w + bb.w;
            h2s[g] = hh;
        }
        {
            float m = stats[2], rs = stats[3];
            float4 v = x2s[NG_D + g], hh;
            hh.x = (v.x - m) * rs * gg.x + bb.x;
            hh.y = (v.y - m) * rs * gg.y + bb.y;
            hh.z = (v.z - m) * rs * gg.z + bb.z;
            hh.w = (v.w - m) * rs * gg.w + bb.w;
            h2s[NG_D + g] = hh;
        }
    }
    __syncthreads();

    // ---- FF1 (K=196, 2 slices of 98) + GELU ----
    float4 f0 = make_float4(0.f,0.f,0.f,0.f), f1 = f0;
    if (tid < 392) {
        const int s1 = tid / NG_MLP;           // 0..1
        const int gg = tid - s1 * NG_MLP;      // <196
        const float* hh0 = (const float*)h2s;          // 196 floats row0
        const float* hh1 = hh0 + D_;                   // row1
        const int kb = s1 * 98;
        const float4* W = ffw1_4 + kb * NG_MLP + gg;
        #pragma unroll 7
        for (int k = 0; k < 98; k++) {
            float4 w = W[k * NG_MLP];
            fma4(f0, hh0[kb + k], w);
            fma4(f1, hh1[kb + k], w);
        }
        if (s1 == 1) {
            red1[gg * 2 + 0] = f0;
            red1[gg * 2 + 1] = f1;
        }
    }
    __syncthreads();
    if (tid < NG_MLP) {
        add4(f0, red1[tid * 2 + 0]);
        add4(f1, red1[tid * 2 + 1]);
        float4 fb = ffb1_4[tid], t0, t1r;
        t0.x = gelu_exact(f0.x + fb.x); t0.y = gelu_exact(f0.y + fb.y);
        t0.z = gelu_exact(f0.z + fb.z); t0.w = gelu_exact(f0.w + fb.w);
        t1r.x = gelu_exact(f1.x + fb.x); t1r.y = gelu_exact(f1.y + fb.y);
        t1r.z = gelu_exact(f1.z + fb.z); t1r.w = gelu_exact(f1.w + fb.w);
        ts4[tid]           = t0;
        ts4[NG_MLP + tid]  = t1r;
    }
    __syncthreads();

    // ---- FF2 (K=784, 8 slices of 98) + residual -> out ----
    float4 o0 = make_float4(0.f,0.f,0.f,0.f), o1 = o0;
    if (s8 < 8) {
        const int kb = s8 * 98;
        const float* t0 = (const float*)ts4;           // 784 floats row0
        const float* t1r = t0 + MLP_;                  // row1
        const float4* W = ffw2_4 + kb * NG_D + g;
        #pragma unroll 7
        for (int k = 0; k < 98; k++) {
            float4 w = W[k * NG_D];
            fma4(o0, t0[kb + k], w);
            fma4(o1, t1r[kb + k], w);
        }
        if (s8 > 0) {
            red2[((s8 - 1) * NG_D + g) * 2 + 0] = o0;
            red2[((s8 - 1) * NG_D + g) * 2 + 1] = o1;
        }
    }
    __syncthreads();
    if (s8 == 0) {
        #pragma unroll
        for (int ss = 0; ss < 7; ss++) {
            add4(o0, red2[(ss * NG_D + g) * 2 + 0]);
            add4(o1, red2[(ss * NG_D + g) * 2 + 1]);
        }
        float4 fb = ffb2_4[g];
        float4 x20 = x2s[g];
        o0.x += fb.x + x20.x; o0.y += fb.y + x20.y;
        o0.z += fb.z + x20.z; o0.w += fb.w + x20.w;
        out4[n0 * NG_D + g] = o0;
        if (v1) {
            float4 x21 = x2s[NG_D + g];
            o1.x += fb.x + x21.x; o1.y += fb.y + x21.y;
            o1.z += fb.z + x21.z; o1.w += fb.w + x21.w;
            out4[n1 * NG_D + g] = o1;
        }
    }
}

// ============================================================
extern "C" void kernel_launch(void* const* d_in, const int* in_sizes, int n_in,
                              void* d_out, int out_size)
{
    const float* x      = (const float*)d_in[0];
    const float* tokens = (const float*)d_in[1];
    const float* x_pe   = (const float*)d_in[2];
    const float* conv_k = (const float*)d_in[3];
    const float* bn_g   = (const float*)d_in[4];
    const float* bn_b   = (const float*)d_in[5];
    const float* bn_rm  = (const float*)d_in[6];
    const float* bn_rv  = (const float*)d_in[7];
    const float* fc_w1  = (const float*)d_in[8];
    const float* fc_w2  = (const float*)d_in[9];
    const float* ln1_g  = (const float*)d_in[10];
    const float* ln1_b  = (const float*)d_in[11];
    const float* ln2_g  = (const float*)d_in[12];
    const float* ln2_b  = (const float*)d_in[13];
    const float* w_qkv  = (const float*)d_in[14];
    const float* w_out  = (const float*)d_in[15];
    const float* b_out  = (const float*)d_in[16];
    const float* ff_w1  = (const float*)d_in[17];
    const float* ff_b1  = (const float*)d_in[18];
    const float* ff_w2  = (const float*)d_in[19];
    const float* ff_b2  = (const float*)d_in[20];

    k_fused<<<GRID_, NT_>>>(x, tokens, x_pe, conv_k, bn_g, bn_b, bn_rm, bn_rv,
                            fc_w1, fc_w2, ln1_g, ln1_b,
                            (const float4*)w_qkv,
                            (const float4*)w_out, (const float4*)b_out,
                            (const float4*)ln2_g, (const float4*)ln2_b,
                            (const float4*)ff_w1, (const float4*)ff_b1,
                            (const float4*)ff_w2, (const float4*)ff_b2,
                            (float4*)d_out);
}